// round 14
// baseline (speedup 1.0000x reference)
#include <cuda_runtime.h>
#include <cuda_fp16.h>
#include <cstdint>
#include <math.h>

constexpr int C = 1024;

// ---- smem byte offsets ----
constexpr uint32_t XB   = 0;        // X: 128 rows x 272B (S1 A operand only)
constexpr uint32_t MISC = 34816;
constexpr uint32_t SMEM_DYN = 35904;
constexpr uint32_t RSB = 272;

// ---- fragment-ordered weight arena ----
// unit = 16k x 16n B-block, 512B (32 lanes x 16B: {b0,b1,b2,b3} per lane, ldsm4t layout).
// stage unit bases: S1=0(64u) S2=64(32u) S3=96(32u) S4=128(64u) S5=192(32u); 224 units.
constexpr int S1U = 0, S2U = 64, S3U = 96, S4U = 128, S5U = 192;
__device__ __align__(16) unsigned char g_wf[224 * 512];
__device__ float g_adj[2 * C];

__device__ __forceinline__ float clip5f(float v) { return fminf(fmaxf(v, -5.f), 5.f); }
__device__ __forceinline__ float sigmf(float v) {
    return __fdividef(1.f, 1.f + __expf(-v));
}
__device__ __forceinline__ float tanh_ap(float x) {
    float y;
    asm("tanh.approx.f32 %0, %1;" : "=f"(y) : "f"(x));
    return y;
}
__device__ __forceinline__ float sigm_ap(float x) {
    return fmaf(tanh_ap(0.5f * x), 0.5f, 0.5f);
}

__device__ __forceinline__ uint32_t smem_u32(const void* p) {
    uint32_t a;
    asm("{ .reg .u64 t; cvta.to.shared.u64 t, %1; cvt.u32.u64 %0, t; }" : "=r"(a) : "l"(p));
    return a;
}
__device__ __forceinline__ void ldsm4(uint32_t* r, uint32_t a) {
    asm volatile("ldmatrix.sync.aligned.m8n8.x4.shared.b16 {%0,%1,%2,%3}, [%4];"
                 : "=r"(r[0]), "=r"(r[1]), "=r"(r[2]), "=r"(r[3]) : "r"(a));
}
__device__ __forceinline__ void mma16816(float* d, const uint32_t* a, const uint32_t* b) {
    asm volatile("mma.sync.aligned.m16n8k16.row.col.f32.f16.f16.f32 "
                 "{%0,%1,%2,%3}, {%4,%5,%6,%7}, {%8,%9}, {%0,%1,%2,%3};"
                 : "+f"(d[0]), "+f"(d[1]), "+f"(d[2]), "+f"(d[3])
                 : "r"(a[0]), "r"(a[1]), "r"(a[2]), "r"(a[3]), "r"(b[0]), "r"(b[1]));
}
__device__ __forceinline__ uint32_t packH2(float f0, float f1) {
    uint32_t h;
    asm("cvt.rn.f16x2.f32 %0, %1, %2;" : "=r"(h) : "f"(f1), "f"(f0));
    return h;
}
__device__ __forceinline__ void storeH2(uint32_t addr, float f0, float f1) {
    uint32_t h = packH2(f0, f1);
    asm volatile("st.shared.b32 [%0], %1;" :: "r"(addr), "r"(h));
}

// 4 units (16k x 64n) from fragment arena: wl = (uint4*)g_wf + lane
__device__ __forceinline__ void mma4(float (*d8)[4], const uint32_t a[4],
                                     const uint4* __restrict__ wl, int u0) {
#pragma unroll
    for (int p = 0; p < 4; ++p) {
        uint4 bf = __ldg(&wl[(u0 + p) * 32]);
        uint32_t b01[2] = {bf.x, bf.y};
        uint32_t b23[2] = {bf.z, bf.w};
        mma16816(d8[2 * p],     a, b01);
        mma16816(d8[2 * p + 1], a, b23);
    }
}

// ---------------- adj precompute (sparse) ------------------------------------------------
__global__ void adj_kernel(const int* __restrict__ qt, const float* __restrict__ onehot,
                           const float* __restrict__ graphs) {
    __shared__ int nnz;
    __shared__ int idxs[1024];
    __shared__ float wts[1024];
    __shared__ float denom;
    int d = threadIdx.x, k = blockIdx.x;
    const float* a0 = onehot + (size_t)qt[0] * C;
    float a = a0[d];
    if (d == 0) nnz = 0;
    __syncthreads();
    if (a != 0.f) { int p = atomicAdd(&nnz, 1); idxs[p] = d; wts[p] = a; }
    __syncthreads();
    if (d == 0) {
        float s = 0.f;
        for (int i = 0; i < nnz; ++i) s += wts[i];
        denom = fmaxf(s, 1.f);
    }
    __syncthreads();
    float s = 0.f;
    int m = nnz;
    for (int i = 0; i < m; ++i)
        s = fmaf(wts[i], graphs[((size_t)k * C + idxs[i]) * C + d], s);
    g_adj[k * C + d] = clip5f(s / denom);
}

// ---------------- weight prep: fragment-ordered fp16 B units -----------------------------
// m16n8k16 B fragment: reg j holds {B[k0+(lane%4)*2 + 8j][n0+lane/4], B[k.. +1][..]};
// unit's 4 regs = two n8 tiles (n0, n0+8).
__global__ void prep_kernel(const float* __restrict__ Wn1, const float* __restrict__ Wn2,
                            const float* __restrict__ We,  const float* __restrict__ Wa,
                            const float* __restrict__ Wih, const float* __restrict__ Whh) {
    int gid = blockIdx.x * 256 + threadIdx.x;
    if (gid >= 224 * 32) return;
    int unit = gid >> 5, lane = gid & 31;
    int stage, lu;
    if (unit < S2U)      { stage = 1; lu = unit; }
    else if (unit < S3U) { stage = 2; lu = unit - S2U; }
    else if (unit < S4U) { stage = 3; lu = unit - S3U; }
    else if (unit < S5U) { stage = 4; lu = unit - S4U; }
    else                 { stage = 5; lu = unit - S5U; }
    int kcu = lu >> 3, nc = lu & 7;
    int k0 = kcu * 16 + (lane & 3) * 2;
    int n0 = nc * 16 + (lane >> 2);

    auto W = [&](int k, int n) -> float {
        switch (stage) {
        case 1: return (n < 64) ? Wn1[(size_t)(128 + k) * 64 + n]
                                : Wn1[(size_t)(256 + 128 + k) * 64 + (n - 64)];
        case 2: return (n < 64) ? Wn2[(size_t)k * 64 + n]
                                : Wn2[(size_t)(64 + k) * 64 + (n - 64)];
        case 3: return (n < 64) ? We[(size_t)k * 64 + n] : Wa[(size_t)k * 64 + (n - 64)];
        case 4: return (k < 64) ? Wih[(size_t)k * 192 + n] : Whh[(size_t)(k - 64) * 192 + n];
        default:return (n < 64) ? Wih[(size_t)k * 192 + 128 + n]
                                : Whh[(size_t)k * 192 + 128 + (n - 64)];
        }
    };
    uint4 v;
    v.x = packH2(W(k0,     n0),     W(k0 + 1, n0));
    v.y = packH2(W(k0 + 8, n0),     W(k0 + 9, n0));
    v.z = packH2(W(k0,     n0 + 8), W(k0 + 1, n0 + 8));
    v.w = packH2(W(k0 + 8, n0 + 8), W(k0 + 9, n0 + 8));
    *(uint4*)(g_wf + (size_t)unit * 512 + lane * 16) = v;
}

// ---------------- main fused kernel ------------------------------------------------------
__global__ void __launch_bounds__(256, 2)
fused_kernel(const int* __restrict__ qt, const float* __restrict__ ht,
             const float* __restrict__ onehot, const float* __restrict__ kc,
             const float* __restrict__ nwp,
             const float* __restrict__ Ws1, const float* __restrict__ bs1,
             const float* __restrict__ Ws2, const float* __restrict__ bs2,
             const float* __restrict__ bn1, const float* __restrict__ bn2,
             const float* __restrict__ ea,  const float* __restrict__ be,
             const float* __restrict__ ba,  const float* __restrict__ bih,
             const float* __restrict__ bhh, const float* __restrict__ Wp,
             const float* __restrict__ bp, float* __restrict__ out) {
    extern __shared__ __align__(16) char sm[];
    const uint32_t smb = smem_u32(sm);

    const int tid = threadIdx.x;
    const int warp = tid >> 5, lane = tid & 31;
    const int q = lane & 3, trow = lane >> 2;
    const int R0 = warp * 16 + trow, R1 = R0 + 8;
    const int r0 = blockIdx.x * 128;
    const int b  = r0 >> 10;
    const int cb0 = r0 & (C - 1);

    const int lrow = (lane & 7) + ((lane & 8) ? 8 : 0);
    const int lhi8 = (lane & 16) ? 8 : 0;
    const uint4* __restrict__ wl = ((const uint4*)g_wf) + lane;

    int* mcount = (int*)(sm + MISC);
    int* mrows  = (int*)(sm + MISC + 16);
    float* self1 = (float*)(sm + MISC + 528);
    float* selfo = (float*)(sm + MISC + 784);

    const float nw = fminf(fmaxf(nwp[0], 0.1f), 0.9f);
    const int qtb  = qt[b];
    const float bp0 = bp[0];
    const float adjA0 = g_adj[cb0 + R0], adjA1 = g_adj[cb0 + R1];
    const float adjB0 = g_adj[C + cb0 + R0], adjB1 = g_adj[C + cb0 + R1];
    const float eav0 = ea[cb0 + R0], eav1 = ea[cb0 + R1];
    const float* hp0 = ht + (size_t)(r0 + R0) * 64;
    const float* hp1 = ht + (size_t)(r0 + R1) * 64;

    if (tid == 0) *mcount = 0;
    __syncthreads();
    if (tid < 128 && onehot[(size_t)qtb * C + cb0 + tid] > 0.5f) {
        int p = atomicAdd(mcount, 1);
        mrows[p] = tid;
    }

    // ---- build X = [fp16(clip5 ht) | fp16(clip5 kc)] (S1 A operand) ----
    {
        int row = tid >> 1, half = tid & 1;
        const float* src = half ? (kc + (size_t)(cb0 + row) * 64) : (ht + (size_t)(r0 + row) * 64);
        uint32_t rowb = smb + XB + (uint32_t)row * RSB + (uint32_t)half * 128;
#pragma unroll
        for (int i = 0; i < 16; ++i) {
            float4 v = ((const float4*)src)[i];
            storeH2(rowb + i * 8,     clip5f(v.x), clip5f(v.y));
            storeH2(rowb + i * 8 + 4, clip5f(v.z), clip5f(v.w));
        }
    }
    __syncthreads();

    uint32_t af1[16][2];
    float m[8][4];
    uint32_t afr[8][2], afh[8][2];
    uint32_t rgp[8][2], zgp[8][2];

    // ================= S1: nb1_0 | nb1_1 (A from smem X) =================
    {
        float d[16][4] = {};
        const uint32_t aA = smb + XB + (uint32_t)(warp * 16 + lrow) * RSB + lhi8 * 2;
#pragma unroll
        for (int kcu = 0; kcu < 8; ++kcu) {
            uint32_t a[4];
            ldsm4(a, aA + kcu * 32);
            mma4(d,     a, wl, S1U + kcu * 8);
            mma4(d + 8, a, wl, S1U + kcu * 8 + 4);
        }
#pragma unroll
        for (int nb = 0; nb < 16; ++nb) {
            int c = 8 * nb + 2 * q;
            float b0 = bn1[c], b1 = bn1[c + 1];
            af1[nb][0] = packH2(fmaxf(d[nb][0] + b0, 0.f), fmaxf(d[nb][1] + b1, 0.f));
            af1[nb][1] = packH2(fmaxf(d[nb][2] + b0, 0.f), fmaxf(d[nb][3] + b1, 0.f));
        }
    }
    // ================= S2: split nb2 (A = af1 regs) =================
    {
        float d[16][4] = {};
#pragma unroll
        for (int h = 0; h < 2; ++h)
#pragma unroll
            for (int kcu = 0; kcu < 4; ++kcu) {
                uint32_t a[4] = {af1[8 * h + 2 * kcu][0], af1[8 * h + 2 * kcu][1],
                                 af1[8 * h + 2 * kcu + 1][0], af1[8 * h + 2 * kcu + 1][1]};
                mma4(&d[8 * h], a, wl, S2U + kcu * 8 + 4 * h);
            }
        float wn = 1.f - nw;
#pragma unroll
        for (int nb = 0; nb < 8; ++nb) {
            int c = 8 * nb + 2 * q;
            float b00 = bn2[c], b01 = bn2[c + 1];
            float b10 = bn2[64 + c], b11 = bn2[64 + c + 1];
#pragma unroll
            for (int e = 0; e < 4; ++e) {
                float adjA = (e < 2) ? adjA0 : adjA1;
                float adjB = (e < 2) ? adjB0 : adjB1;
                float bb0 = (e & 1) ? b01 : b00;
                float bb1 = (e & 1) ? b11 : b10;
                float nb0 = fminf(fmaxf(d[nb][e] + bb0, 0.f), 5.f);
                float nb1 = fminf(fmaxf(d[nb + 8][e] + bb1, 0.f), 5.f);
                float t = clip5f(adjA * nb0);
                m[nb][e] = clip5f(nw * t + wn * adjB * nb1);
            }
        }
    }
    // ---- self path for masked rows (rare) ----
    __syncthreads();
    {
        int mc = *mcount;
        for (int mi = 0; mi < mc; ++mi) {
            int rr = mrows[mi];
            if (tid < 64) {
                const float* hrow = ht + (size_t)(r0 + rr) * 64;
                const float* krow = kc + (size_t)(cb0 + rr) * 64;
                float s = bs1[tid];
                for (int i = 0; i < 64; ++i) s = fmaf(hrow[i], Ws1[i * 64 + tid], s);
                for (int i = 0; i < 64; ++i) s = fmaf(krow[i], Ws1[(64 + i) * 64 + tid], s);
                self1[tid] = fmaxf(s, 0.f);
            }
            __syncthreads();
            if (tid < 64) {
                float s = bs2[tid];
                for (int i = 0; i < 64; ++i) s = fmaf(self1[i], Ws2[i * 64 + tid], s);
                selfo[tid] = fminf(fmaxf(s, 0.f), 10.f);
            }
            __syncthreads();
            if (R0 == rr)
#pragma unroll
                for (int nb = 0; nb < 8; ++nb) {
                    m[nb][0] = selfo[8 * nb + 2 * q];
                    m[nb][1] = selfo[8 * nb + 2 * q + 1];
                }
            if (R1 == rr)
#pragma unroll
                for (int nb = 0; nb < 8; ++nb) {
                    m[nb][2] = selfo[8 * nb + 2 * q];
                    m[nb][3] = selfo[8 * nb + 2 * q + 1];
                }
            __syncthreads();
        }
    }
    // ================= S3: We | Wa (A = m regs); res -> afr =================
    {
        float d[16][4] = {};
#pragma unroll
        for (int kcu = 0; kcu < 4; ++kcu) {
            uint32_t a[4] = {packH2(m[2 * kcu][0], m[2 * kcu][1]),
                             packH2(m[2 * kcu][2], m[2 * kcu][3]),
                             packH2(m[2 * kcu + 1][0], m[2 * kcu + 1][1]),
                             packH2(m[2 * kcu + 1][2], m[2 * kcu + 1][3])};
            mma4(d,     a, wl, S3U + kcu * 8);
            mma4(d + 8, a, wl, S3U + kcu * 8 + 4);
        }
#pragma unroll
        for (int nb = 0; nb < 8; ++nb) {
            int c = 8 * nb + 2 * q;
            float be0 = be[c], be1 = be[c + 1];
            float ba0 = ba[c], ba1 = ba[c + 1];
            float res[4];
#pragma unroll
            for (int e = 0; e < 4; ++e) {
                float eav = (e < 2) ? eav0 : eav1;
                float sg = sigm_ap(d[nb][e] + ((e & 1) ? be1 : be0));
                float th = tanh_ap(d[nb + 8][e] + ((e & 1) ? ba1 : ba0));
                res[e] = m[nb][e] - eav * sg * m[nb][e] + eav * th;
            }
            afr[nb][0] = packH2(res[0], res[1]);
            afr[nb][1] = packH2(res[2], res[3]);
        }
    }
    // ---- raw-ht fragments ----
#pragma unroll
    for (int nb = 0; nb < 8; ++nb) {
        int c = 8 * nb + 2 * q;
        float2 v0 = *(const float2*)(hp0 + c);
        float2 v1 = *(const float2*)(hp1 + c);
        afh[nb][0] = packH2(v0.x, v0.y);
        afh[nb][1] = packH2(v1.x, v1.y);
    }
    // ================= S4: GRU r | z (A = [afr|afh]) =================
    {
        float d[16][4] = {};
#pragma unroll
        for (int kcu = 0; kcu < 4; ++kcu) {
            uint32_t a[4] = {afr[2 * kcu][0], afr[2 * kcu][1],
                             afr[2 * kcu + 1][0], afr[2 * kcu + 1][1]};
            mma4(d,     a, wl, S4U + kcu * 8);
            mma4(d + 8, a, wl, S4U + kcu * 8 + 4);
        }
#pragma unroll
        for (int kcu = 0; kcu < 4; ++kcu) {
            uint32_t a[4] = {afh[2 * kcu][0], afh[2 * kcu][1],
                             afh[2 * kcu + 1][0], afh[2 * kcu + 1][1]};
            mma4(d,     a, wl, S4U + (kcu + 4) * 8);
            mma4(d + 8, a, wl, S4U + (kcu + 4) * 8 + 4);
        }
#pragma unroll
        for (int nb = 0; nb < 8; ++nb) {
            int c = 8 * nb + 2 * q;
            float br0 = bih[c] + bhh[c], br1 = bih[c + 1] + bhh[c + 1];
            float bz0 = bih[64 + c] + bhh[64 + c], bz1 = bih[64 + c + 1] + bhh[64 + c + 1];
            rgp[nb][0] = packH2(sigm_ap(d[nb][0] + br0), sigm_ap(d[nb][1] + br1));
            rgp[nb][1] = packH2(sigm_ap(d[nb][2] + br0), sigm_ap(d[nb][3] + br1));
            zgp[nb][0] = packH2(sigm_ap(d[nb + 8][0] + bz0), sigm_ap(d[nb + 8][1] + bz1));
            zgp[nb][1] = packH2(sigm_ap(d[nb + 8][2] + bz0), sigm_ap(d[nb + 8][3] + bz1));
        }
    }
    // ================= S5: split in|hn ; GRU fuse ; output dot =================
    {
        float d[16][4] = {};
#pragma unroll
        for (int kcu = 0; kcu < 4; ++kcu) {
            uint32_t a[4] = {afr[2 * kcu][0], afr[2 * kcu][1],
                             afr[2 * kcu + 1][0], afr[2 * kcu + 1][1]};
            mma4(d, a, wl, S5U + kcu * 8);
        }
#pragma unroll
        for (int kcu = 0; kcu < 4; ++kcu) {
            uint32_t a[4] = {afh[2 * kcu][0], afh[2 * kcu][1],
                             afh[2 * kcu + 1][0], afh[2 * kcu + 1][1]};
            mma4(d + 8, a, wl, S5U + kcu * 8 + 4);
        }
        float p0 = 0.f, p1 = 0.f;
#pragma unroll
        for (int nb = 0; nb < 8; ++nb) {
            int c = 8 * nb + 2 * q;
            float bi0 = bih[128 + c], bi1 = bih[128 + c + 1];
            float bh0 = bhh[128 + c], bh1 = bhh[128 + c + 1];
            float w0 = Wp[c], w1 = Wp[c + 1];
            float2 rg0 = __half22float2(*(__half2*)&rgp[nb][0]);
            float2 rg1 = __half22float2(*(__half2*)&rgp[nb][1]);
            float2 zg0 = __half22float2(*(__half2*)&zgp[nb][0]);
            float2 zg1 = __half22float2(*(__half2*)&zgp[nb][1]);
            float n00 = tanh_ap(d[nb][0] + bi0 + rg0.x * (d[nb + 8][0] + bh0));
            float n01 = tanh_ap(d[nb][1] + bi1 + rg0.y * (d[nb + 8][1] + bh1));
            float n10 = tanh_ap(d[nb][2] + bi0 + rg1.x * (d[nb + 8][2] + bh0));
            float n11 = tanh_ap(d[nb][3] + bi1 + rg1.y * (d[nb + 8][3] + bh1));
            float h00 = (1.f - zg0.x) * n00 + zg0.x * hp0[c];
            float h01 = (1.f - zg0.y) * n01 + zg0.y * hp0[c + 1];
            float h10 = (1.f - zg1.x) * n10 + zg1.x * hp1[c];
            float h11 = (1.f - zg1.y) * n11 + zg1.y * hp1[c + 1];
            p0 = fmaf(h00, w0, fmaf(h01, w1, p0));
            p1 = fmaf(h10, w0, fmaf(h11, w1, p1));
        }
        p0 += __shfl_xor_sync(0xffffffffu, p0, 1);
        p0 += __shfl_xor_sync(0xffffffffu, p0, 2);
        p1 += __shfl_xor_sync(0xffffffffu, p1, 1);
        p1 += __shfl_xor_sync(0xffffffffu, p1, 2);
        if (q == 0) {
            out[r0 + R0] = sigmf(p0 + bp0);
            out[r0 + R1] = sigmf(p1 + bp0);
        }
    }
}

// ---------------- launch -----------------------------------------------------------------
extern "C" void kernel_launch(void* const* d_in, const int* in_sizes, int n_in,
                              void* d_out, int out_size) {
    const int*   qt     = (const int*)d_in[1];
    const float* ht     = (const float*)d_in[2];
    const float* onehot = (const float*)d_in[3];
    const float* kc     = (const float*)d_in[4];
    const float* graphs = (const float*)d_in[5];
    const float* nw     = (const float*)d_in[6];
    const float* Ws1    = (const float*)d_in[7];
    const float* bs1    = (const float*)d_in[8];
    const float* Ws2    = (const float*)d_in[9];
    const float* bs2    = (const float*)d_in[10];
    const float* Wn1    = (const float*)d_in[11];
    const float* bn1    = (const float*)d_in[12];
    const float* Wn2    = (const float*)d_in[13];
    const float* bn2    = (const float*)d_in[14];
    const float* ea     = (const float*)d_in[15];
    const float* We     = (const float*)d_in[16];
    const float* be     = (const float*)d_in[17];
    const float* Wa     = (const float*)d_in[18];
    const float* ba     = (const float*)d_in[19];
    const float* Wih    = (const float*)d_in[20];
    const float* bih    = (const float*)d_in[21];
    const float* Whh    = (const float*)d_in[22];
    const float* bhh    = (const float*)d_in[23];
    const float* Wp     = (const float*)d_in[24];
    const float* bp     = (const float*)d_in[25];
    float* out = (float*)d_out;

    cudaFuncSetAttribute(fused_kernel, cudaFuncAttributeMaxDynamicSharedMemorySize, SMEM_DYN);

    adj_kernel<<<2, 1024>>>(qt, onehot, graphs);
    prep_kernel<<<(224 * 32 + 255) / 256, 256>>>(Wn1, Wn2, We, Wa, Wih, Whh);
    fused_kernel<<<2048, 256, SMEM_DYN>>>(
        qt, ht, onehot, kc, nw, Ws1, bs1, Ws2, bs2, bn1, bn2,
        ea, be, ba, bih, bhh, Wp, bp, out);
}